// round 1
// baseline (speedup 1.0000x reference)
#include <cuda_runtime.h>

// Fused: upsample2x_bilinear -> affine_grid -> grid_sample_bilinear
// x: (8, 32, 256, 256) f32, theta: (8, 2, 3) f32, out: (8, 32, 512, 512) f32
//
// Composition is separable: per output (n, y, x) the value is a 3x3 weighted
// sum over the ORIGINAL image, with per-axis weights combining the grid-sample
// bilinear taps (incl. zero-padding validity) and the upsample-2x taps.

#define N_   8
#define C_   32
#define HI   256
#define WI   256
#define HU   512
#define WU   512

// Compute combined per-axis taps: base original index + 3 weights.
// f    : grid-sample fractional coordinate in upsampled space
// U    : upsampled size (512), O: original size (256)
__device__ __forceinline__ void axis_taps(float f, int U, int O,
                                          int& base, float w[3]) {
    float f0 = floorf(f);
    int   i0 = (int)f0;
    float wf = f - f0;

    w[0] = 0.f; w[1] = 0.f; w[2] = 0.f;
    base = 0;

    #pragma unroll
    for (int k = 0; k < 2; k++) {
        int   t  = i0 + k;
        float Wk = (k == 0) ? (1.0f - wf) : wf;
        // zero-padding validity (separable)
        Wk = (t >= 0 && t < U) ? Wk : 0.0f;
        int tc = min(max(t, 0), U - 1);
        // upsample source: s = (tc+0.5)/2 - 0.5 = tc*0.5 - 0.25, clamped at 0
        float s  = fmaxf((float)tc * 0.5f - 0.25f, 0.0f);
        int   o0 = (int)s;              // s >= 0, trunc == floor
        float wu = s - (float)o0;
        int   o1 = min(o0 + 1, O - 1);
        if (k == 0) base = o0;          // monotone: later taps have o >= base
        w[o0 - base] += Wk * (1.0f - wu);
        w[o1 - base] += Wk * wu;
    }
}

__global__ void __launch_bounds__(256)
fused_upsample_affine_sample(const float* __restrict__ x,
                             const float* __restrict__ theta,
                             float* __restrict__ out) {
    int tid = blockIdx.x * blockDim.x + threadIdx.x;
    int xo = tid & (WU - 1);
    int yo = (tid >> 9) & (HU - 1);
    int n  = tid >> 18;

    // affine grid (match reference op order)
    float gxn = (2.0f * (float)xo + 1.0f) / (float)WU - 1.0f;
    float gyn = (2.0f * (float)yo + 1.0f) / (float)HU - 1.0f;
    const float* th = theta + n * 6;
    float t0 = __ldg(th + 0), t1 = __ldg(th + 1), t2 = __ldg(th + 2);
    float t3 = __ldg(th + 3), t4 = __ldg(th + 4), t5 = __ldg(th + 5);
    float gox = t0 * gxn + t1 * gyn + t2;
    float goy = t3 * gxn + t4 * gyn + t5;

    // grid_sample source coords in upsampled space
    float ix = ((gox + 1.0f) * (float)WU - 1.0f) * 0.5f;
    float iy = ((goy + 1.0f) * (float)HU - 1.0f) * 0.5f;

    float* op = out + (((long long)n * C_) * (long long)(HU * WU))
                    + (long long)yo * WU + xo;

    // Fully out of bounds (both taps invalid on either axis) -> zeros.
    float ixf = floorf(ix), iyf = floorf(iy);
    int ix0 = (int)ixf, iy0 = (int)iyf;
    bool oob = (ix0 < -1) || (ix0 >= WU) || (iy0 < -1) || (iy0 >= HU)
               || !(ix == ix) || !(iy == iy);
    if (oob) {
        #pragma unroll 8
        for (int c = 0; c < C_; c++)
            op[(long long)c * (HU * WU)] = 0.0f;
        return;
    }

    int by, bx;
    float wy[3], wx[3];
    axis_taps(iy, HU, HI, by, wy);
    axis_taps(ix, WU, WI, bx, wx);

    // Precompute 9 offsets (clamped to stay in-bounds; weights are 0 there)
    int ro[3], co[3];
    #pragma unroll
    for (int i = 0; i < 3; i++) {
        ro[i] = min(by + i, HI - 1) * WI;
        co[i] = min(bx + i, WI - 1);
    }
    int   off[9];
    float wgt[9];
    #pragma unroll
    for (int i = 0; i < 3; i++)
        #pragma unroll
        for (int j = 0; j < 3; j++) {
            off[i * 3 + j] = ro[i] + co[j];
            wgt[i * 3 + j] = wy[i] * wx[j];
        }

    const float* xp = x + (long long)n * C_ * (HI * WI);

    #pragma unroll 4
    for (int c = 0; c < C_; c++) {
        const float* p = xp + c * (HI * WI);
        float v = 0.0f;
        #pragma unroll
        for (int k = 0; k < 9; k++)
            v = fmaf(wgt[k], __ldg(p + off[k]), v);
        op[(long long)c * (HU * WU)] = v;
    }
}

extern "C" void kernel_launch(void* const* d_in, const int* in_sizes, int n_in,
                              void* d_out, int out_size) {
    const float* x     = (const float*)d_in[0];
    const float* theta = (const float*)d_in[1];
    float*       out   = (float*)d_out;

    int total = N_ * HU * WU;            // one thread per (n, y, x); loops C
    int block = 256;
    int grid  = total / block;           // 8192, exact
    fused_upsample_affine_sample<<<grid, block>>>(x, theta, out);
}

// round 2
// speedup vs baseline: 1.0546x; 1.0546x over previous
#include <cuda_runtime.h>

// Fused upsample2x-bilinear -> affine_grid -> grid_sample_bilinear.
// Composition is separable: each output = 3x3 weighted sum over ORIGINAL image.
// R2: float2-vectorized x-taps (6 LDG.64/channel) + 8x4 warp tiles.

#define N_   8
#define C_   32
#define HI   256
#define WI   256
#define HU   512
#define WU   512

__device__ __forceinline__ void axis_taps(float f, int U, int O,
                                          int& base, float w[3]) {
    float f0 = floorf(f);
    int   i0 = (int)f0;
    float wf = f - f0;

    w[0] = 0.f; w[1] = 0.f; w[2] = 0.f;
    base = 0;

    #pragma unroll
    for (int k = 0; k < 2; k++) {
        int   t  = i0 + k;
        float Wk = (k == 0) ? (1.0f - wf) : wf;
        Wk = (t >= 0 && t < U) ? Wk : 0.0f;          // zero-padding validity
        int tc = min(max(t, 0), U - 1);
        float s  = fmaxf((float)tc * 0.5f - 0.25f, 0.0f);  // upsample source
        int   o0 = (int)s;
        float wu = s - (float)o0;
        int   o1 = min(o0 + 1, O - 1);
        if (k == 0) base = o0;                       // taps are monotone
        w[o0 - base] += Wk * (1.0f - wu);
        w[o1 - base] += Wk * wu;
    }
}

__global__ void __launch_bounds__(256)
fused_upsample_affine_sample(const float* __restrict__ x,
                             const float* __restrict__ theta,
                             float* __restrict__ out) {
    // 8x4 warp tiles: lane = (lx in [0,8), ly in [0,4))
    int wid  = blockIdx.x * 8 + (threadIdx.x >> 5);
    int lane = threadIdx.x & 31;
    int xo = ((wid & 63) << 3) | (lane & 7);          // 64 tiles of 8 in x
    int yo = (((wid >> 6) & 127) << 2) | (lane >> 3); // 128 tiles of 4 in y
    int n  = wid >> 13;

    // affine grid (reference op order)
    float gxn = (2.0f * (float)xo + 1.0f) / (float)WU - 1.0f;
    float gyn = (2.0f * (float)yo + 1.0f) / (float)HU - 1.0f;
    const float* th = theta + n * 6;
    float gox = __ldg(th + 0) * gxn + __ldg(th + 1) * gyn + __ldg(th + 2);
    float goy = __ldg(th + 3) * gxn + __ldg(th + 4) * gyn + __ldg(th + 5);

    float ix = ((gox + 1.0f) * (float)WU - 1.0f) * 0.5f;
    float iy = ((goy + 1.0f) * (float)HU - 1.0f) * 0.5f;

    float* op = out + (((long long)n * C_) * (long long)(HU * WU))
                    + (long long)yo * WU + xo;

    int ix0 = (int)floorf(ix), iy0 = (int)floorf(iy);
    bool oob = (ix0 < -1) || (ix0 >= WU) || (iy0 < -1) || (iy0 >= HU)
               || !(ix == ix) || !(iy == iy);
    if (oob) {
        #pragma unroll 8
        for (int c = 0; c < C_; c++)
            op[(long long)c * (HU * WU)] = 0.0f;
        return;
    }

    int by, bx;
    float wy[3], wx[3];
    axis_taps(iy, HU, HI, by, wy);
    axis_taps(ix, WU, WI, bx, wx);

    // x-taps live at columns bx..bx+2; cover with aligned 4-wide window [e, e+3].
    // Weights wx[j] with shift+j > 3 are provably zero (edge folding in axis_taps).
    int e     = min(bx & ~1, WI - 4);
    int shift = bx - e;                 // 0..3
    float wv0 = (shift == 0) ? wx[0] : 0.0f;
    float wv1 = (shift == 0) ? wx[1] : (shift == 1) ? wx[0] : 0.0f;
    float wv2 = (shift == 0) ? wx[2] : (shift == 1) ? wx[1]
              : (shift == 2) ? wx[0] : 0.0f;
    float wv3 = (shift == 1) ? wx[2] : (shift == 2) ? wx[1]
              : (shift == 3) ? wx[0] : 0.0f;

    // 3 rows x 4 cols separable weights
    float w00 = wy[0]*wv0, w01 = wy[0]*wv1, w02 = wy[0]*wv2, w03 = wy[0]*wv3;
    float w10 = wy[1]*wv0, w11 = wy[1]*wv1, w12 = wy[1]*wv2, w13 = wy[1]*wv3;
    float w20 = wy[2]*wv0, w21 = wy[2]*wv1, w22 = wy[2]*wv2, w23 = wy[2]*wv3;

    int r0 = min(by,     HI - 1) * WI + e;   // rows beyond edge have wy=0
    int r1 = min(by + 1, HI - 1) * WI + e;
    int r2 = min(by + 2, HI - 1) * WI + e;

    const float* xp = x + (long long)n * C_ * (HI * WI);

    #pragma unroll 4
    for (int c = 0; c < C_; c++) {
        const float* p = xp + c * (HI * WI);
        float2 a0 = __ldg((const float2*)(p + r0));
        float2 b0 = __ldg((const float2*)(p + r0 + 2));
        float2 a1 = __ldg((const float2*)(p + r1));
        float2 b1 = __ldg((const float2*)(p + r1 + 2));
        float2 a2 = __ldg((const float2*)(p + r2));
        float2 b2 = __ldg((const float2*)(p + r2 + 2));

        float v = 0.0f;
        v = fmaf(w00, a0.x, v); v = fmaf(w01, a0.y, v);
        v = fmaf(w02, b0.x, v); v = fmaf(w03, b0.y, v);
        v = fmaf(w10, a1.x, v); v = fmaf(w11, a1.y, v);
        v = fmaf(w12, b1.x, v); v = fmaf(w13, b1.y, v);
        v = fmaf(w20, a2.x, v); v = fmaf(w21, a2.y, v);
        v = fmaf(w22, b2.x, v); v = fmaf(w23, b2.y, v);

        op[(long long)c * (HU * WU)] = v;
    }
}

extern "C" void kernel_launch(void* const* d_in, const int* in_sizes, int n_in,
                              void* d_out, int out_size) {
    const float* x     = (const float*)d_in[0];
    const float* theta = (const float*)d_in[1];
    float*       out   = (float*)d_out;

    // 65536 warps total (8x4 tile each), 8 warps per block
    fused_upsample_affine_sample<<<8192, 256>>>(x, theta, out);
}